// round 3
// baseline (speedup 1.0000x reference)
#include <cuda_runtime.h>

// DiffAugment fused single persistent kernel.
// B=128, C=3, H=W=256 fp32. shift=32, cut=51 (half=25).
//
// Identity: global mean after brightness+saturation == mean(x_raw) + (r_bright-0.5).
//
// Structure: 1024 blocks, 8 blocks per batch.
//  Phase A: each block reduces 1/8 of its batch (6144 float4).
//           Last arriver of the 8 publishes g_mean[b] (fence + flag).
//  Phase B: same 8 blocks spin (ns-sleep) on their batch's flag, then run the
//           fused color/translate/cutout on 32 rows x 3 channels each.
//  Batch data stays L2-resident between phases; batches pipeline independently.
// All state (partials/flags/counters) is reset by the last finishing block so
// every graph replay starts from zeros (deterministic).

#define EPB 196608   // 3*256*256

__device__ float         g_part[1024];
__device__ float         g_mean[128];
__device__ unsigned int  g_arrive[128];   // zero-init
__device__ volatile int  g_ready[128];    // zero-init
__device__ unsigned int  g_done;          // zero-init

__global__ void __launch_bounds__(256, 8) fused_kernel(
    const float* __restrict__ x,
    const float* __restrict__ rb, const float* __restrict__ rs, const float* __restrict__ rc,
    const int* __restrict__ txv, const int* __restrict__ tyv,
    const int* __restrict__ oxv, const int* __restrict__ oyv,
    float* __restrict__ out)
{
    const int bid = blockIdx.x;       // 0..1023
    const int t   = threadIdx.x;      // 0..255
    const int b   = bid >> 3;         // batch owned by this block

    // ---------------- Phase A: reduce chunk `bid` (1/8 of batch b) ----------
    {
        const float4* p = reinterpret_cast<const float4*>(x) + (size_t)bid * 6144 + t;
        float s = 0.f;
#pragma unroll
        for (int k = 0; k < 24; ++k) {
            float4 v = p[k * 256];
            s += (v.x + v.y) + (v.z + v.w);
        }
#pragma unroll
        for (int o = 16; o; o >>= 1) s += __shfl_down_sync(0xffffffffu, s, o);
        __shared__ float sh[8];
        if ((t & 31) == 0) sh[t >> 5] = s;
        __syncthreads();
        if (t == 0) {
            s = sh[0] + sh[1] + sh[2] + sh[3] + sh[4] + sh[5] + sh[6] + sh[7];
            g_part[bid] = s;
            __threadfence();
            unsigned old = atomicAdd(&g_arrive[b], 1u);
            if (old == 7u) {            // last arriver aggregates + publishes
                const float* gp = g_part + 8 * b;
                float tot = ((gp[0] + gp[1]) + (gp[2] + gp[3]))
                          + ((gp[4] + gp[5]) + (gp[6] + gp[7]));
                g_mean[b] = tot * (1.0f / 196608.0f);
                __threadfence();
                g_ready[b] = 1;
            }
        }
    }

    // ---------------- wait for this batch's mean ----------------------------
    __shared__ float s_g, s_rbm, s_s2, s_cc;
    __shared__ int   s_tx, s_ty, s_ox, s_oy;
    if (t == 0) {
        while (g_ready[b] == 0) __nanosleep(60);
        __threadfence();
        float rbm = __ldg(rb + b) - 0.5f;
        s_rbm = rbm;
        s_g   = g_mean[b] + rbm;
        s_s2  = __ldg(rs + b) * 2.0f;
        s_cc  = __ldg(rc + b) + 0.5f;
        s_tx  = __ldg(txv + b) - 32;
        s_ty  = __ldg(tyv + b) - 32;
        s_ox  = __ldg(oxv + b);
        s_oy  = __ldg(oyv + b);
    }
    __syncthreads();

    const float rbm = s_rbm, g = s_g, s2 = s_s2, cc = s_cc;
    const int tx = s_tx, ty = s_ty, ox = s_ox, oy = s_oy;

    // ---------------- Phase B: aug 32 rows x 3 channels of batch b ----------
    const int rg0 = (bid & 7) * 8;          // 8 rowgroups of 4 rows each
    const int w0  = (t & 63) << 2;          // 4 consecutive columns
    const float* xb0 = x   + (size_t)b * EPB;
    float*       ob0 = out + (size_t)b * EPB;

#pragma unroll
    for (int k = 0; k < 8; ++k) {
        const int h = (rg0 + k) * 4 + (t >> 6);
        const int src_h = h + tx;
        const bool row_ok  = ((unsigned)src_h) < 256u;
        const bool cut_row = (h >= ox - 25) && (h <= ox + 25);
        const float* xb = xb0 + src_h * 256;

        float r0[4], r1[4], r2[4];
#pragma unroll
        for (int j = 0; j < 4; ++j) {
            int w  = w0 + j;
            int sw = w + ty;
            bool ok = row_ok && ((unsigned)sw < 256u) &&
                      !(cut_row && (w >= oy - 25) && (w <= oy + 25));
            float a0 = 0.f, a1 = 0.f, a2 = 0.f;
            if (ok) {
                float v0 = xb[sw];
                float v1 = xb[sw + 65536];
                float v2 = xb[sw + 131072];
                float m  = (v0 + v1 + v2) * (1.0f / 3.0f);
                float mb = m + rbm;
                a0 = fmaf(fmaf(v0 - m, s2, mb) - g, cc, g);
                a1 = fmaf(fmaf(v1 - m, s2, mb) - g, cc, g);
                a2 = fmaf(fmaf(v2 - m, s2, mb) - g, cc, g);
            }
            r0[j] = a0; r1[j] = a1; r2[j] = a2;
        }

        size_t o = (size_t)h * 256 + w0;
        __stcs(reinterpret_cast<float4*>(ob0 + o),
               make_float4(r0[0], r0[1], r0[2], r0[3]));
        __stcs(reinterpret_cast<float4*>(ob0 + o + 65536),
               make_float4(r1[0], r1[1], r1[2], r1[3]));
        __stcs(reinterpret_cast<float4*>(ob0 + o + 131072),
               make_float4(r2[0], r2[1], r2[2], r2[3]));
    }

    // ---------------- reset state for the next graph replay -----------------
    __syncthreads();
    if (t == 0) {
        unsigned old = atomicAdd(&g_done, 1u);
        if (old == 1023u) {
            for (int i = 0; i < 128; ++i) { g_arrive[i] = 0u; g_ready[i] = 0; }
            g_done = 0u;
            __threadfence();
        }
    }
}

extern "C" void kernel_launch(void* const* d_in, const int* in_sizes, int n_in,
                              void* d_out, int out_size) {
    const float* x  = (const float*)d_in[0];
    const float* rb = (const float*)d_in[1];
    const float* rs = (const float*)d_in[2];
    const float* rc = (const float*)d_in[3];
    const int*   tx = (const int*)d_in[4];
    const int*   ty = (const int*)d_in[5];
    const int*   ox = (const int*)d_in[6];
    const int*   oy = (const int*)d_in[7];
    float* out = (float*)d_out;

    fused_kernel<<<1024, 256>>>(x, rb, rs, rc, tx, ty, ox, oy, out);
}

// round 5
// speedup vs baseline: 1.0814x; 1.0814x over previous
#include <cuda_runtime.h>

// DiffAugment, two-kernel version.
// B=128, C=3, H=W=256 fp32. shift=32, cut=51 (half=25).
// Identity: global mean after brightness+saturation == mean(x_raw) + (r_bright-0.5).
//
// R4: aug stages source rows into smem via aligned float4 loads (kills the
//     misaligned 2-sector scalar LDGs), computes with conflict-free strided
//     LDS; sum limits front-batched MLP to 4 to avoid L1tex-queue spread.

#define EPB 196608   // 3*256*256

__device__ float g_part[1024];   // 8 partials per batch

__global__ void __launch_bounds__(256) sum_kernel(const float* __restrict__ x) {
    int blk = blockIdx.x;           // 0..1023 : batch = blk>>3
    int t = threadIdx.x;
    const float4* p = reinterpret_cast<const float4*>(x) + (size_t)blk * 6144 + t;
    float s = 0.f;
#pragma unroll 1
    for (int k0 = 0; k0 < 24; k0 += 4) {
        float4 a = p[(k0 + 0) * 256];
        float4 b = p[(k0 + 1) * 256];
        float4 c = p[(k0 + 2) * 256];
        float4 d = p[(k0 + 3) * 256];
        s += ((a.x + a.y) + (a.z + a.w)) + ((b.x + b.y) + (b.z + b.w))
           + ((c.x + c.y) + (c.z + c.w)) + ((d.x + d.y) + (d.z + d.w));
    }
#pragma unroll
    for (int o = 16; o; o >>= 1) s += __shfl_down_sync(0xffffffffu, s, o);
    __shared__ float sh[8];
    if ((t & 31) == 0) sh[t >> 5] = s;
    __syncthreads();
    if (t == 0) {
        g_part[blk] = sh[0] + sh[1] + sh[2] + sh[3] + sh[4] + sh[5] + sh[6] + sh[7];
    }
}

// Each block: one batch b, 4 output rows h0..h0+3, all 3 channels.
// Stage: 12 source rows (3 ch x 4 rows) as aligned float4 -> smem (12 KB).
// Compute: thread (r = t>>6, c = t&63) handles cols {c, c+64, c+128, c+192}.
__global__ void __launch_bounds__(256) aug_kernel(
    const float* __restrict__ x,
    const float* __restrict__ rb, const float* __restrict__ rs, const float* __restrict__ rc,
    const int* __restrict__ txv, const int* __restrict__ tyv,
    const int* __restrict__ oxv, const int* __restrict__ oyv,
    float* __restrict__ out)
{
    __shared__ float sm[12 * 256];          // [ch*4 + r][col]

    const int blk = blockIdx.x;             // 0..8191
    const int t   = threadIdx.x;
    const int b   = blk >> 6;
    const int h0  = (blk & 63) << 2;

    const int tx = __ldg(txv + b) - 32;
    const int ty = __ldg(tyv + b) - 32;
    const int ox = __ldg(oxv + b);
    const int oy = __ldg(oyv + b);

    const float rbm = __ldg(rb + b) - 0.5f;
    const float s2  = __ldg(rs + b) * 2.0f;
    const float cc  = __ldg(rc + b) + 0.5f;
    const float4* gp = reinterpret_cast<const float4*>(g_part) + 2 * b;
    float4 p0 = gp[0], p1 = gp[1];
    const float g = (((p0.x + p0.y) + (p0.z + p0.w)) + ((p1.x + p1.y) + (p1.z + p1.w)))
                    * (1.0f / 196608.0f) + rbm;

    // ---- stage 12 rows, aligned float4, zero-fill OOB rows ----
    {
        const float4* xb4 = reinterpret_cast<const float4*>(x) + (size_t)b * 49152;
        float4* smv = reinterpret_cast<float4*>(sm);
#pragma unroll
        for (int i = 0; i < 3; ++i) {
            int e    = t + i * 256;          // 0..767
            int rcix = e >> 6;               // 0..11 = ch*4 + r
            int col4 = e & 63;
            int ch   = rcix >> 2;
            int r    = rcix & 3;
            int sr   = h0 + r + tx;
            float4 v = make_float4(0.f, 0.f, 0.f, 0.f);
            if ((unsigned)sr < 256u)
                v = xb4[ch * 16384 + sr * 64 + col4];
            smv[rcix * 64 + col4] = v;
        }
    }
    __syncthreads();

    // ---- compute + store ----
    const int r = t >> 6;                    // 0..3
    const int c = t & 63;
    const int h = h0 + r;
    const bool row_ok  = ((unsigned)(h + tx)) < 256u;
    const bool cut_row = (h >= ox - 25) && (h <= ox + 25);

    const float* s0 = sm + (0 * 4 + r) * 256;
    const float* s1 = sm + (1 * 4 + r) * 256;
    const float* s2r = sm + (2 * 4 + r) * 256;
    float* ob = out + (size_t)b * EPB + h * 256;

#pragma unroll
    for (int j = 0; j < 4; ++j) {
        int w  = c + (j << 6);
        int sw = w + ty;
        bool inb = (unsigned)sw < 256u;
        float v0 = inb ? s0[sw]  : 0.f;
        float v1 = inb ? s1[sw]  : 0.f;
        float v2 = inb ? s2r[sw] : 0.f;
        bool ok = row_ok && inb &&
                  !(cut_row && (w >= oy - 25) && (w <= oy + 25));
        float m  = (v0 + v1 + v2) * (1.0f / 3.0f);
        float mb = m + rbm;
        float a0 = fmaf(fmaf(v0 - m, s2, mb) - g, cc, g);
        float a1 = fmaf(fmaf(v1 - m, s2, mb) - g, cc, g);
        float a2 = fmaf(fmaf(v2 - m, s2, mb) - g, cc, g);
        __stcs(ob + w,           ok ? a0 : 0.f);
        __stcs(ob + w + 65536,   ok ? a1 : 0.f);
        __stcs(ob + w + 131072,  ok ? a2 : 0.f);
    }
}

extern "C" void kernel_launch(void* const* d_in, const int* in_sizes, int n_in,
                              void* d_out, int out_size) {
    const float* x  = (const float*)d_in[0];
    const float* rb = (const float*)d_in[1];
    const float* rs = (const float*)d_in[2];
    const float* rc = (const float*)d_in[3];
    const int*   tx = (const int*)d_in[4];
    const int*   ty = (const int*)d_in[5];
    const int*   ox = (const int*)d_in[6];
    const int*   oy = (const int*)d_in[7];
    float* out = (float*)d_out;

    sum_kernel<<<1024, 256>>>(x);
    aug_kernel<<<8192, 256>>>(x, rb, rs, rc, tx, ty, ox, oy, out);
}